// round 15
// baseline (speedup 1.0000x reference)
#include <cuda_runtime.h>
#include <cuda_bf16.h>
#include <mma.h>
#include <math.h>
#include <stdint.h>

#define VV 10000
#define NPAD 10112
#define EE 512
#define HH 1024
#define SS 64
#define BB 64

#define SBH (SS*BB*HH)
#define BH  (BB*HH)

typedef unsigned long long ull;
typedef __nv_bfloat16 bf;
namespace wm = nvcuda::wmma;

// ---------------- device scratch ----------------
__device__ float g_X0[3u * SBH];
__device__ float g_H1all[SBH];
__device__ float g_h0[2][BH];   // layer0 hidden, parity: H(t) in g_h0[t&1]
__device__ float g_x1[2][BH];   // fc output, parity t&1
__device__ float g_h1[BH];
__device__ float g_rh0[BH];
__device__ float g_z0[BH];
__device__ float g_rh1[BH];
__device__ float g_z1[BH];
// wmma k_out operands (bf16 hi/lo)
__device__ __align__(16) bf g_WoH[1024 * NPAD];
__device__ __align__(16) bf g_WoL[1024 * NPAD];
__device__ __align__(16) bf g_H1H[SBH];
__device__ __align__(16) bf g_H1L[SBH];

__device__ __forceinline__ float sigm(float x) { return 1.0f / (1.0f + __expf(-x)); }

// ---------------- packed f32x2 helpers (sm_103a FFMA2) ----------------
__device__ __forceinline__ void fma2(ull &c, ull a, ull b) {
    asm("fma.rn.f32x2 %0, %1, %2, %0;" : "+l"(c) : "l"(a), "l"(b));
}
__device__ __forceinline__ void add2(ull &c, ull a) {
    asm("add.rn.f32x2 %0, %0, %1;" : "+l"(c) : "l"(a));
}
__device__ __forceinline__ ull pk2(float lo, float hi) {
    ull r; asm("mov.b64 %0, {%1, %2};" : "=l"(r) : "f"(lo), "f"(hi)); return r;
}
__device__ __forceinline__ void unpk(ull v, float &lo, float &hi) {
    asm("mov.b64 {%0, %1}, %2;" : "=f"(lo), "=f"(hi) : "l"(v));
}

// ---------------- init ----------------
__global__ void k_init(const float* __restrict__ h_init) {
    int i = blockIdx.x * blockDim.x + threadIdx.x;
    if (i < BH) {
        g_h0[0][i] = h_init[i];
        g_h1[i]    = h_init[BH + i];
    }
}

// ---------------- Wout pad + bf16 hi/lo split ----------------
__global__ void k_woconv(const float* __restrict__ Wout) {
    long long idx = (long long)blockIdx.x * blockDim.x + threadIdx.x;
    if (idx >= 1024LL * NPAD) return;
    int k = (int)(idx / NPAD), n = (int)(idx % NPAD);
    float v = (n < VV) ? Wout[(size_t)k * VV + n] : 0.f;
    bf h = __float2bfloat16(v);
    g_WoH[idx] = h;
    g_WoL[idx] = __float2bfloat16(v - __bfloat162float(h));
}

// ---------------- H1all bf16 hi/lo split (after scan) ----------------
__global__ void k_h1conv() {
    int idx = blockIdx.x * blockDim.x + threadIdx.x;
    if (idx < SBH) {
        float v = g_H1all[idx];
        bf h = __float2bfloat16(v);
        g_H1H[idx] = h;
        g_H1L[idx] = __float2bfloat16(v - __bfloat162float(h));
    }
}

// ---------------- embedding precompute GEMM (fp32, packed fma2) ----------------
__global__ __launch_bounds__(256) void k_embed(
    const int* __restrict__ ids, const float* __restrict__ emb,
    const float* __restrict__ Wr, const float* __restrict__ Wz, const float* __restrict__ Wh,
    const float* __restrict__ br, const float* __restrict__ bz, const float* __restrict__ bh)
{
    const int g = blockIdx.z;
    const float* __restrict__ W    = (g == 0) ? Wr : ((g == 1) ? Wz : Wh);
    const float* __restrict__ bias = (g == 0) ? br : ((g == 1) ? bz : bh);
    float* __restrict__ out = g_X0 + (size_t)g * SBH;
    __shared__ __align__(16) float As[16][68];
    __shared__ __align__(16) float Ws[16][64];
    const int tid = threadIdx.x;
    const int bm = blockIdx.y * 64, bn = blockIdx.x * 64;
    const int lr = tid >> 2, lk = (tid & 3) * 4;
    const int wk = tid >> 4, wn = (tid & 15) * 4;
    const int tx = tid & 15, ty = tid >> 4;
    const float* __restrict__ arow = emb + (size_t)ids[bm + lr] * EE + lk;
    ull accp[4][2];
#pragma unroll
    for (int i = 0; i < 4; i++) { accp[i][0] = 0ull; accp[i][1] = 0ull; }
    for (int k0 = 0; k0 < EE; k0 += 16) {
        float4 av = *(const float4*)(arow + k0);
        As[lk + 0][lr] = av.x; As[lk + 1][lr] = av.y;
        As[lk + 2][lr] = av.z; As[lk + 3][lr] = av.w;
        *(float4*)&Ws[wk][wn] = *(const float4*)(W + (size_t)(k0 + wk) * HH + bn + wn);
        __syncthreads();
#pragma unroll
        for (int kk = 0; kk < 16; kk++) {
            float4 a = *(const float4*)&As[kk][ty * 4];
            float4 w = *(const float4*)&Ws[kk][tx * 4];
            ulonglong2 wp = *reinterpret_cast<ulonglong2*>(&w);
            ull a0 = pk2(a.x, a.x), a1 = pk2(a.y, a.y);
            ull a2 = pk2(a.z, a.z), a3 = pk2(a.w, a.w);
            fma2(accp[0][0], a0, wp.x); fma2(accp[0][1], a0, wp.y);
            fma2(accp[1][0], a1, wp.x); fma2(accp[1][1], a1, wp.y);
            fma2(accp[2][0], a2, wp.x); fma2(accp[2][1], a2, wp.y);
            fma2(accp[3][0], a3, wp.x); fma2(accp[3][1], a3, wp.y);
        }
        __syncthreads();
    }
    float4 bv = *(const float4*)(bias + bn + tx * 4);
#pragma unroll
    for (int i = 0; i < 4; i++) {
        float c0, c1, c2, c3;
        unpk(accp[i][0], c0, c1); unpk(accp[i][1], c2, c3);
        float* o = out + (size_t)(bm + ty * 4 + i) * HH + bn + tx * 4;
        o[0] = c0 + bv.x; o[1] = c1 + bv.y; o[2] = c2 + bv.z; o[3] = c3 + bv.w;
    }
}

// ================= wmma k_out: logits = H1all @ Wout + bout =================
// CTA tile 128m x 128n, K=1024, k-chunks of 16, bf16 hi/lo 3-term, fp32 acc.
// smem: 2 bufs x (Ah 4K | Al 4K | Bh 4K | Bl 4K) = 32KB; C overlay 64KB.
#define KOUT_SMEM (64 * 1024)

__global__ __launch_bounds__(256) void k_outw(
    const float* __restrict__ bout, float* __restrict__ logits)
{
    extern __shared__ char dyn[];
    const int tid = threadIdx.x;
    const int bn = blockIdx.x * 128;
    const int bm = blockIdx.y * 128;
    const int wid = tid >> 5;
    const int m0 = (wid & 3) * 32, n0 = (wid >> 2) * 64;

    // loader mapping (each thread loads one 16-elem A segment + one 16-elem B segment)
    const int part = tid >> 7;                 // 0 hi, 1 lo
    const int arow = tid & 127;                // A row (batch)
    const int kr = (tid >> 3) & 15, seg = tid & 7;   // B: k-row, 16-col segment

    const bf* __restrict__ Asrc = (part ? g_H1L : g_H1H) + (size_t)(bm + arow) * 1024;
    const bf* __restrict__ Bsrc = (part ? g_WoL : g_WoH) + bn + seg * 16;

    wm::fragment<wm::accumulator, 16, 16, 16, float> acc[2][4];
#pragma unroll
    for (int i = 0; i < 2; i++)
#pragma unroll
        for (int j = 0; j < 4; j++) wm::fill_fragment(acc[i][j], 0.0f);

    uint4 ra0, ra1, rb0, rb1;
    // prologue: chunk 0
    {
        const bf* a = Asrc;                       ra0 = *(const uint4*)a; ra1 = *(const uint4*)(a + 8);
        const bf* b = Bsrc + (size_t)kr * NPAD;   rb0 = *(const uint4*)b; rb1 = *(const uint4*)(b + 8);
    }
    {
        bf* Ad = (bf*)(dyn + part * 4096) + arow * 16;
        bf* Bd = (bf*)(dyn + 8192 + part * 4096) + kr * 128 + seg * 16;
        *(uint4*)Ad = ra0; *(uint4*)(Ad + 8) = ra1;
        *(uint4*)Bd = rb0; *(uint4*)(Bd + 8) = rb1;
    }
    __syncthreads();

    int buf = 0;
    for (int c = 0; c < 64; ++c) {
        const bool more = (c + 1 < 64);
        if (more) {
            const int k0 = (c + 1) * 16;
            const bf* a = Asrc + k0;                        ra0 = *(const uint4*)a; ra1 = *(const uint4*)(a + 8);
            const bf* b = Bsrc + (size_t)(k0 + kr) * NPAD;  rb0 = *(const uint4*)b; rb1 = *(const uint4*)(b + 8);
        }
        {
            const bf* Ah = (const bf*)(dyn + buf * 16384);
            const bf* Al = (const bf*)(dyn + buf * 16384 + 4096);
            const bf* Bh = (const bf*)(dyn + buf * 16384 + 8192);
            const bf* Bl = (const bf*)(dyn + buf * 16384 + 12288);
            wm::fragment<wm::matrix_a, 16, 16, 16, bf, wm::row_major> ah0, ah1, al0, al1;
            wm::load_matrix_sync(ah0, Ah + (m0 + 0) * 16, 16);
            wm::load_matrix_sync(ah1, Ah + (m0 + 16) * 16, 16);
            wm::load_matrix_sync(al0, Al + (m0 + 0) * 16, 16);
            wm::load_matrix_sync(al1, Al + (m0 + 16) * 16, 16);
#pragma unroll
            for (int j = 0; j < 4; j++) {
                wm::fragment<wm::matrix_b, 16, 16, 16, bf, wm::row_major> bh, bl;
                wm::load_matrix_sync(bh, Bh + n0 + j * 16, 128);
                wm::load_matrix_sync(bl, Bl + n0 + j * 16, 128);
                wm::mma_sync(acc[0][j], ah0, bh, acc[0][j]);
                wm::mma_sync(acc[0][j], ah0, bl, acc[0][j]);
                wm::mma_sync(acc[0][j], al0, bh, acc[0][j]);
                wm::mma_sync(acc[1][j], ah1, bh, acc[1][j]);
                wm::mma_sync(acc[1][j], ah1, bl, acc[1][j]);
                wm::mma_sync(acc[1][j], al1, bh, acc[1][j]);
            }
        }
        if (more) {
            bf* Ad = (bf*)(dyn + (buf ^ 1) * 16384 + part * 4096) + arow * 16;
            bf* Bd = (bf*)(dyn + (buf ^ 1) * 16384 + 8192 + part * 4096) + kr * 128 + seg * 16;
            *(uint4*)Ad = ra0; *(uint4*)(Ad + 8) = ra1;
            *(uint4*)Bd = rb0; *(uint4*)(Bd + 8) = rb1;
            __syncthreads();
            buf ^= 1;
        }
    }

    // overlay C on the A/B buffers
    __syncthreads();
    float* Cs = (float*)dyn;
#pragma unroll
    for (int i = 0; i < 2; i++)
#pragma unroll
        for (int j = 0; j < 4; j++)
            wm::store_matrix_sync(Cs + (m0 + i * 16) * 128 + n0 + j * 16, acc[i][j], 128, wm::mem_row_major);
    __syncthreads();

    for (int e = tid; e < 128 * 128; e += 256) {
        int r = e >> 7, cc = e & 127;
        int gn = bn + cc;
        if (gn < VV)
            logits[(size_t)(bm + r) * VV + gn] = Cs[e] + bout[gn];
    }
}

// ================= R11 SIMT stage GEMM core (proven, 9.17 ms) =================
#define SM16 ((8*2*8*68 + 8*2*8*32) * 4 + 7*64*8*8)    // 79872 B
#define SM32 ((4*2*8*68 + 4*2*8*64) * 4 + 3*128*8*8)   // 58368 B

template<int NC, int KT, int KT1>
__device__ __forceinline__ void stage_core(
    const float* __restrict__ A1, const float* __restrict__ A2,
    const float* __restrict__ W, int bn, ull* __restrict__ acc)
{
    constexpr int NCP = NC / 2;
    constexpr int TPT = 8 * NCP;
    constexpr int NTEAM = 512 / TPT;
    constexpr int KTEAM = KT / NTEAM;
    constexpr int CH = KTEAM / 8;
    constexpr int ASF = NTEAM * 2 * 8 * 68;
    constexpr int WSF = NTEAM * 2 * 8 * 2 * NC;

    extern __shared__ float dynf[];
    float* As = dynf;
    float* Ws = dynf + ASF;
    ull*   Pq = (ull*)(dynf + ASF + WSF);

    const int tid = threadIdx.x;
    const int team = tid / TPT, u = tid % TPT;
    const int koff = team * KTEAM;
    const float* __restrict__ Ab = (koff < KT1) ? (A1 + koff) : (A2 + (koff - KT1));

    const int arow = (NC == 16) ? u : (u >> 1);
    const int akh  = (NC == 16) ? 0 : ((u & 1) * 4);
    const int wr   = (NC == 16) ? (u >> 3) : (u >> 4);
    const int wq   = (NC == 16) ? (u & 7)  : (u & 15);
    const int rg = u / NCP, cp = u % NCP;

    const float* __restrict__ Ap = Ab + (size_t)arow * HH + akh;
    const float* __restrict__ Wp = W + (size_t)(koff + wr) * HH + bn + wq * 2;

#pragma unroll
    for (int i = 0; i < 8; i++) acc[i] = 0ull;

    float a_st[(NC == 16) ? 8 : 4];
    float w0s, w1s;

    {
        float4 v0 = *(const float4*)(Ap);
        a_st[0]=v0.x; a_st[1]=v0.y; a_st[2]=v0.z; a_st[3]=v0.w;
        if (NC == 16) {
            float4 v1 = *(const float4*)(Ap + 4);
            a_st[4]=v1.x; a_st[5]=v1.y; a_st[6]=v1.z; a_st[7]=v1.w;
        }
        float2 wv = *(const float2*)(Wp);
        w0s = wv.x; w1s = wv.y;
    }
    {
        float* Abs = As + (team * 2) * 544;
        if (NC == 16) {
#pragma unroll
            for (int j = 0; j < 8; j++) Abs[j * 68 + u] = a_st[j];
        } else {
#pragma unroll
            for (int j = 0; j < 4; j++) Abs[(akh + j) * 68 + arow] = a_st[j];
        }
        float* Wd = Ws + (team * 2) * (16 * NC) + wr * (2 * NC) + wq * 4;
        Wd[0] = w0s; Wd[1] = w0s; Wd[2] = w1s; Wd[3] = w1s;
    }
    __syncthreads();

    int buf = 0;
    for (int c = 0; c < CH; ++c) {
        const bool more = (c + 1 < CH);
        if (more) {
            const int k0 = (c + 1) * 8;
            float4 v0 = *(const float4*)(Ap + k0);
            a_st[0]=v0.x; a_st[1]=v0.y; a_st[2]=v0.z; a_st[3]=v0.w;
            if (NC == 16) {
                float4 v1 = *(const float4*)(Ap + k0 + 4);
                a_st[4]=v1.x; a_st[5]=v1.y; a_st[6]=v1.z; a_st[7]=v1.w;
            }
            float2 wv = *(const float2*)(Wp + (size_t)k0 * HH);
            w0s = wv.x; w1s = wv.y;
        }
        {
            const float* Ac = As + (team * 2 + buf) * 544 + rg * 8;
            const float* Wc = Ws + (team * 2 + buf) * (16 * NC) + cp * 4;
#pragma unroll
            for (int kk = 0; kk < 8; ++kk) {
                float4 lo = *(const float4*)(Ac + kk * 68);
                float4 hi = *(const float4*)(Ac + kk * 68 + 4);
                float4 wd = *(const float4*)(Wc + kk * 2 * NC);
                ulonglong2 pl = *reinterpret_cast<ulonglong2*>(&lo);
                ulonglong2 ph = *reinterpret_cast<ulonglong2*>(&hi);
                ulonglong2 wp = *reinterpret_cast<ulonglong2*>(&wd);
                fma2(acc[0], pl.x, wp.x); fma2(acc[1], pl.x, wp.y);
                fma2(acc[2], pl.y, wp.x); fma2(acc[3], pl.y, wp.y);
                fma2(acc[4], ph.x, wp.x); fma2(acc[5], ph.x, wp.y);
                fma2(acc[6], ph.y, wp.x); fma2(acc[7], ph.y, wp.y);
            }
        }
        if (more) {
            float* Abs = As + (team * 2 + (buf ^ 1)) * 544;
            if (NC == 16) {
#pragma unroll
                for (int j = 0; j < 8; j++) Abs[j * 68 + u] = a_st[j];
            } else {
#pragma unroll
                for (int j = 0; j < 4; j++) Abs[(akh + j) * 68 + arow] = a_st[j];
            }
            float* Wd = Ws + (team * 2 + (buf ^ 1)) * (16 * NC) + wr * (2 * NC) + wq * 4;
            Wd[0] = w0s; Wd[1] = w0s; Wd[2] = w1s; Wd[3] = w1s;
            __syncthreads();
            buf ^= 1;
        }
    }

    if (team != 0) {
        ull* p = Pq + (size_t)(team - 1) * TPT * 8 + u * 8;
#pragma unroll
        for (int i = 0; i < 8; i++) p[i] = acc[i];
    }
    __syncthreads();
    if (team == 0) {
#pragma unroll 1
        for (int r = 0; r < NTEAM - 1; r++) {
            ull* p = Pq + (size_t)r * TPT * 8 + u * 8;
#pragma unroll
            for (int i = 0; i < 8; i++) add2(acc[i], p[i]);
        }
    }
}

// ---------------- stage kernels (R11, grid=64, block=512) ----------------
__global__ __launch_bounds__(512, 1) void k_g0(int p, int ts,
    const float* __restrict__ Wr0, const float* __restrict__ Wz0)
{
    const int g = blockIdx.x * 32;
    const int gate = g >> 10, bn = g & (HH - 1);
    const float* W = (gate ? Wz0 : Wr0) + (size_t)EE * HH;
    ull acc[8];
    stage_core<32, HH, HH>(g_h0[p], g_h0[p], W, bn, acc);
    if (threadIdx.x < 128) {
        const int u = threadIdx.x, rg = u >> 4, cp = u & 15;
        const float* X = g_X0 + (size_t)gate * SBH + (size_t)ts * BH;
        const float* h0 = g_h0[p];
#pragma unroll
        for (int q = 0; q < 4; q++)
#pragma unroll
            for (int c = 0; c < 2; c++) {
                float va, vb; unpk(acc[2 * q + c], va, vb);
                int r = rg * 8 + 2 * q, n = bn + cp * 2 + c;
                int i0 = r * HH + n, i1 = i0 + HH;
                float s0 = sigm(va + X[i0]);
                float s1 = sigm(vb + X[i1]);
                if (gate == 0) { g_rh0[i0] = s0 * h0[i0]; g_rh0[i1] = s1 * h0[i1]; }
                else           { g_z0[i0] = s0;           g_z0[i1] = s1; }
            }
    }
}

__global__ __launch_bounds__(512, 1) void k_c0(int p, int ts, const float* __restrict__ Wh0)
{
    const int bn = blockIdx.x * 16;
    ull acc[8];
    stage_core<16, HH, HH>(g_rh0, g_rh0, Wh0 + (size_t)EE * HH, bn, acc);
    if (threadIdx.x < 64) {
        const int u = threadIdx.x, rg = u >> 3, cp = u & 7;
        const float* X = g_X0 + 2ull * SBH + (size_t)ts * BH;
        const float* h0 = g_h0[p];
        float* h0n = g_h0[p ^ 1];
#pragma unroll
        for (int q = 0; q < 4; q++)
#pragma unroll
            for (int c = 0; c < 2; c++) {
                float va, vb; unpk(acc[2 * q + c], va, vb);
                int r = rg * 8 + 2 * q, n = bn + cp * 2 + c;
                int i0 = r * HH + n, i1 = i0 + HH;
                float za = g_z0[i0], zb = g_z0[i1];
                h0n[i0] = (1.f - za) * h0[i0] + za * sigm(va + X[i0]);
                h0n[i1] = (1.f - zb) * h0[i1] + zb * sigm(vb + X[i1]);
            }
    }
}

__global__ __launch_bounds__(512, 1) void k_fc(int ph, int px,
    const float* __restrict__ Wfc, const float* __restrict__ bfc)
{
    const int bn = blockIdx.x * 16;
    ull acc[8];
    stage_core<16, HH, HH>(g_h0[ph], g_h0[ph], Wfc, bn, acc);
    if (threadIdx.x < 64) {
        const int u = threadIdx.x, rg = u >> 3, cp = u & 7;
        float* x1 = g_x1[px];
#pragma unroll
        for (int q = 0; q < 4; q++)
#pragma unroll
            for (int c = 0; c < 2; c++) {
                float va, vb; unpk(acc[2 * q + c], va, vb);
                int r = rg * 8 + 2 * q, n = bn + cp * 2 + c;
                x1[r * HH + n]       = sigm(va + bfc[n]);
                x1[(r + 1) * HH + n] = sigm(vb + bfc[n]);
            }
    }
}

__global__ __launch_bounds__(512, 1) void k_g1(int p,
    const float* __restrict__ Wr1, const float* __restrict__ Wz1,
    const float* __restrict__ br1, const float* __restrict__ bz1)
{
    const int g = blockIdx.x * 32;
    const int gate = g >> 10, bn = g & (HH - 1);
    const float* W = gate ? Wz1 : Wr1;
    ull acc[8];
    stage_core<32, 2 * HH, HH>(g_x1[p], g_h1, W, bn, acc);
    if (threadIdx.x < 128) {
        const int u = threadIdx.x, rg = u >> 4, cp = u & 15;
        const float* bias = gate ? bz1 : br1;
#pragma unroll
        for (int q = 0; q < 4; q++)
#pragma unroll
            for (int c = 0; c < 2; c++) {
                float va, vb; unpk(acc[2 * q + c], va, vb);
                int r = rg * 8 + 2 * q, n = bn + cp * 2 + c;
                int i0 = r * HH + n, i1 = i0 + HH;
                float s0 = sigm(va + bias[n]);
                float s1 = sigm(vb + bias[n]);
                if (gate == 0) { g_rh1[i0] = s0 * g_h1[i0]; g_rh1[i1] = s1 * g_h1[i1]; }
                else           { g_z1[i0] = s0;             g_z1[i1] = s1; }
            }
    }
}

__global__ __launch_bounds__(512, 1) void k_c1(int p, int ts,
    const float* __restrict__ Wh1, const float* __restrict__ bh1)
{
    const int bn = blockIdx.x * 16;
    ull acc[8];
    stage_core<16, 2 * HH, HH>(g_x1[p], g_rh1, Wh1, bn, acc);
    if (threadIdx.x < 64) {
        const int u = threadIdx.x, rg = u >> 3, cp = u & 7;
#pragma unroll
        for (int q = 0; q < 4; q++)
#pragma unroll
            for (int c = 0; c < 2; c++) {
                float va, vb; unpk(acc[2 * q + c], va, vb);
                int r = rg * 8 + 2 * q, n = bn + cp * 2 + c;
#pragma unroll
                for (int s = 0; s < 2; s++) {
                    int idx = (r + s) * HH + n;
                    float hv = (s == 0) ? va : vb;
                    float hh = sigm(hv + bh1[n]);
                    float h1 = g_h1[idx], z = g_z1[idx];
                    float hn = (1.f - z) * h1 + z * hh;
                    g_h1[idx] = hn;
                    g_H1all[(size_t)ts * BH + idx] = hn;
                }
            }
    }
}

__global__ void k_hfinal(float* __restrict__ out) {
    int i = blockIdx.x * blockDim.x + threadIdx.x;
    if (i < BH) {
        out[i]      = g_h0[0][i];
        out[BH + i] = g_h1[i];
    }
}

extern "C" void kernel_launch(void* const* d_in, const int* in_sizes, int n_in,
                              void* d_out, int out_size)
{
    const int*   ids    = (const int*)d_in[0];
    const float* h_init = (const float*)d_in[1];
    const float* emb    = (const float*)d_in[2];
    const float* Wr0 = (const float*)d_in[3],  *Wz0 = (const float*)d_in[4],  *Wh0 = (const float*)d_in[5];
    const float* br0 = (const float*)d_in[6],  *bz0 = (const float*)d_in[7],  *bh0 = (const float*)d_in[8];
    const float* Wr1 = (const float*)d_in[9],  *Wz1 = (const float*)d_in[10], *Wh1 = (const float*)d_in[11];
    const float* br1 = (const float*)d_in[12], *bz1 = (const float*)d_in[13], *bh1 = (const float*)d_in[14];
    const float* Wfc = (const float*)d_in[15], *bfc = (const float*)d_in[16];
    const float* Wout = (const float*)d_in[17], *bout = (const float*)d_in[18];
    float* out = (float*)d_out;

    static bool s_init = false;
    static cudaStream_t sB, sC;
    static cudaEvent_t evStart, evC0, evFcP[2], evC1P[2], evB, evC;
    if (!s_init) {
        cudaStreamCreateWithFlags(&sB, cudaStreamNonBlocking);
        cudaStreamCreateWithFlags(&sC, cudaStreamNonBlocking);
        cudaEventCreateWithFlags(&evStart,  cudaEventDisableTiming);
        cudaEventCreateWithFlags(&evC0,     cudaEventDisableTiming);
        cudaEventCreateWithFlags(&evFcP[0], cudaEventDisableTiming);
        cudaEventCreateWithFlags(&evFcP[1], cudaEventDisableTiming);
        cudaEventCreateWithFlags(&evC1P[0], cudaEventDisableTiming);
        cudaEventCreateWithFlags(&evC1P[1], cudaEventDisableTiming);
        cudaEventCreateWithFlags(&evB,      cudaEventDisableTiming);
        cudaEventCreateWithFlags(&evC,      cudaEventDisableTiming);
        s_init = true;
    }

    cudaFuncSetAttribute(k_g0, cudaFuncAttributeMaxDynamicSharedMemorySize, SM32);
    cudaFuncSetAttribute(k_g1, cudaFuncAttributeMaxDynamicSharedMemorySize, SM32);
    cudaFuncSetAttribute(k_c0, cudaFuncAttributeMaxDynamicSharedMemorySize, SM16);
    cudaFuncSetAttribute(k_fc, cudaFuncAttributeMaxDynamicSharedMemorySize, SM16);
    cudaFuncSetAttribute(k_c1, cudaFuncAttributeMaxDynamicSharedMemorySize, SM16);
    cudaFuncSetAttribute(k_outw, cudaFuncAttributeMaxDynamicSharedMemorySize, KOUT_SMEM);

    k_init<<<(BH + 255) / 256, 256>>>(h_init);
    k_woconv<<<(int)((1024LL * NPAD + 255) / 256), 256>>>(Wout);
    k_embed<<<dim3(HH / 64, (SS * BB) / 64, 3), 256>>>(ids, emb, Wr0, Wz0, Wh0, br0, bz0, bh0);

    cudaEventRecord(evStart, 0);
    cudaStreamWaitEvent(sB, evStart, 0);
    cudaStreamWaitEvent(sC, evStart, 0);
    cudaEventRecord(evFcP[0], sB); cudaEventRecord(evFcP[1], sB);
    cudaEventRecord(evC1P[0], sC); cudaEventRecord(evC1P[1], sC);

    for (int t = 0; t < SS; ++t) {
        const int p = t & 1;
        if (t >= 2) cudaStreamWaitEvent(0, evFcP[p], 0);
        k_g0<<<64, 512, SM32, 0>>>(p, t, Wr0, Wz0);
        k_c0<<<64, 512, SM16, 0>>>(p, t, Wh0);
        cudaEventRecord(evC0, 0);
        cudaStreamWaitEvent(sB, evC0, 0);
        if (t >= 2) cudaStreamWaitEvent(sB, evC1P[p], 0);
        k_fc<<<64, 512, SM16, sB>>>(p ^ 1, p, Wfc, bfc);
        cudaEventRecord(evFcP[p], sB);
        cudaStreamWaitEvent(sC, evFcP[p], 0);
        k_g1<<<64, 512, SM32, sC>>>(p, Wr1, Wz1, br1, bz1);
        k_c1<<<64, 512, SM16, sC>>>(p, t, Wh1, bh1);
        cudaEventRecord(evC1P[p], sC);
    }

    cudaEventRecord(evB, sB);
    cudaEventRecord(evC, sC);
    cudaStreamWaitEvent(0, evB, 0);
    cudaStreamWaitEvent(0, evC, 0);

    k_h1conv<<<(SBH + 255) / 256, 256>>>();
    k_outw<<<dim3(NPAD / 128, (SS * BB) / 128), 256, KOUT_SMEM>>>(bout, out);
    k_hfinal<<<(BH + 255) / 256, 256>>>(out + (size_t)SS * BB * VV);
}